// round 4
// baseline (speedup 1.0000x reference)
#include <cuda_runtime.h>

// KernalAnsatz_65481071409588 — GB300 (sm_103a)
//
// Algebraic reduction (R1): the param-dependent circuit unitary C is identical
// for psi_x and psi_y and cancels in the overlap:
//   |<psi_x|psi_y>|^2 = prod_q cos^2((x_q - y_q)/2),  q = 0..22.
//
// R4: latency-bound regime (all pipes 0%, issue 1.6%, duration flat vs
// instruction count). Compress the critical path: 8 lanes x 3 qubits each,
// so the warp product reduction needs 3 SHFL levels (78 cyc) instead of
// 5 (130 cyc). Serial 3-factor product per lane costs ~12 cyc of FMUL;
// 3 MUFU warp-instrs stagger +16 cyc, mostly overlapped. Block = 8 threads.
//
// Inputs (metadata order): x[23] f32, y[23] f32, params[138] f32 (unused —
// cancels exactly). Output: 1 x f32.

#define N_QUBITS 23

__global__ void KernalAnsatz_65481071409588_kernel(const float* __restrict__ x,
                                                   const float* __restrict__ y,
                                                   float* __restrict__ out) {
    const int lane = threadIdx.x;  // 8 threads: lane i owns qubits i, i+8, i+16
    const int q0 = lane;
    const int q1 = lane + 8;
    const int q2 = lane + 16;      // valid only for lane < 7 (q2 <= 22)

    float d0 = (x[q0] - y[q0]) * 0.5f;
    float d1 = (x[q1] - y[q1]) * 0.5f;
    float d2 = (q2 < N_QUBITS) ? (x[q2] - y[q2]) * 0.5f : 0.0f;  // cos(0)=1

    float c0 = __cosf(d0);         // RRO + MUFU.COS each
    float c1 = __cosf(d1);
    float c2 = __cosf(d2);

    float c = (c0 * c1) * c2;
    float p = c * c;

    // 3-level butterfly over 8 lanes.
    #pragma unroll
    for (int off = 4; off > 0; off >>= 1) {
        p *= __shfl_xor_sync(0xFFu, p, off);
    }
    if (lane == 0) {
        out[0] = p;
    }
}

extern "C" void kernel_launch(void* const* d_in, const int* in_sizes, int n_in,
                              void* d_out, int out_size) {
    (void)in_sizes; (void)n_in; (void)out_size;
    const float* x = (const float*)d_in[0];
    const float* y = (const float*)d_in[1];
    // d_in[2] = params — unused: the shared circuit unitary cancels in the overlap.
    float* out = (float*)d_out;
    KernalAnsatz_65481071409588_kernel<<<1, 8>>>(x, y, out);
}

// round 5
// speedup vs baseline: 1.0556x; 1.0556x over previous
#include <cuda_runtime.h>

// KernalAnsatz_65481071409588 — GB300 (sm_103a) — FINAL (reverted to R3 config)
//
// Algebraic reduction (R1): psi_x = C·R(x)|0>, psi_y = C·R(y)|0>, where C
// (the param-dependent rotation layers + CNOT rings) is the SAME unitary for
// both states and cancels in the overlap:
//   |<psi_x|psi_y>|^2 = prod_{q=0}^{22} cos^2((x_q - y_q)/2).
//
// Optimization history:
//   R1 fp64 cos:      6.91 us  (fp64 software cos chain dominated)
//   R2 fp32 cosf:     4.86 us
//   R3 __cosf, 32-ln: 4.61 us  <- best; MUFU.COS, straight-line, 5-lvl shfl
//   R4 8-lane/3-lvl:  4.86 us  (below 256ns timer tick — no real delta)
// All measurements quantized to 256ns ticks; all pipes 0.0%, issue ~2%.
// Remaining time is kernel-launch + graph-replay fixed cost: floor reached.
//
// Numerics: __cosf abs err ~4e-7 over |d|<pi -> <~2e-5 rel on the product;
// measured rel_err 7.1e-5 is the reference's own fp32 rounding. Gate 1e-3.
//
// Inputs (metadata order): x[23] f32, y[23] f32, params[138] f32 (unused —
// cancels exactly). Output: 1 x f32.

#define N_QUBITS 23

__global__ void KernalAnsatz_65481071409588_kernel(const float* __restrict__ x,
                                                   const float* __restrict__ y,
                                                   float* __restrict__ out) {
    const int lane = threadIdx.x;  // one warp
    float d = 0.0f;                // lanes >= N_QUBITS: cos(0) = 1 (identity)
    if (lane < N_QUBITS) {
        d = (x[lane] - y[lane]) * 0.5f;
    }
    float c2 = __cosf(d);          // RRO.SINCOS + MUFU.COS
    c2 *= c2;
    // Warp-wide product reduction (5-level butterfly; inactive lanes hold 1.0).
    #pragma unroll
    for (int off = 16; off > 0; off >>= 1) {
        c2 *= __shfl_xor_sync(0xFFFFFFFFu, c2, off);
    }
    if (lane == 0) {
        out[0] = c2;
    }
}

extern "C" void kernel_launch(void* const* d_in, const int* in_sizes, int n_in,
                              void* d_out, int out_size) {
    (void)in_sizes; (void)n_in; (void)out_size;
    const float* x = (const float*)d_in[0];
    const float* y = (const float*)d_in[1];
    // d_in[2] = params — unused: the shared circuit unitary cancels in the overlap.
    float* out = (float*)d_out;
    KernalAnsatz_65481071409588_kernel<<<1, 32>>>(x, y, out);
}

// round 6
// speedup vs baseline: 1.0629x; 1.0070x over previous
#include <cuda_runtime.h>

// KernalAnsatz_65481071409588 — GB300 (sm_103a) — FINAL
//
// Algebraic reduction: psi_x = C·R(x)|0>, psi_y = C·R(y)|0>, where C (the
// param-dependent RX/RY/RZ layers + CNOT rings, applied twice) is the SAME
// unitary for both states and cancels exactly in the overlap:
//   |<psi_x|psi_y>|^2 = prod_{q=0}^{22} cos^2((x_q - y_q)/2).
// This replaces a 2 x 64MB statevector simulation (>=256MB HBM traffic,
// ~40us at LTS cap) with ~200B of reads and ~60 FLOPs.
//
// Optimization history (timer tick = 256 ns):
//   R1 fp64 cos:        6.91 us   (fp64 software-cos DFMA chain dominated)
//   R2 fp32 cosf:       4.86 us
//   R3 __cosf, 32-lane: 4.61 us   <- best (reproduced R5, R6)
//   R4 8-lane/3-level:  4.86 us   (delta below tick resolution)
// Floor analysis: kernel critical path ~440 cyc (~0.4 us); remaining ~4.2 us
// is grid-launch + graph-replay fixed cost at idle DVFS clocks. All pipes
// 0.0%, DRAM 0.0%, issue 1.4% — nothing on-chip is the bottleneck.
//
// Numerics: __cosf abs err ~4e-7 over |d|<pi -> <~2e-5 rel on the product;
// measured rel_err 7.1e-5 is the reference's own fp32 rounding (stable across
// rounds). Gate: 1e-3.
//
// Inputs (metadata order): x[23] f32, y[23] f32, params[138] f32 (unused —
// cancels exactly). Output: 1 x f32.

#define N_QUBITS 23

__global__ void KernalAnsatz_65481071409588_kernel(const float* __restrict__ x,
                                                   const float* __restrict__ y,
                                                   float* __restrict__ out) {
    const int lane = threadIdx.x;  // one warp
    float d = 0.0f;                // lanes >= N_QUBITS: cos(0) = 1 (identity)
    if (lane < N_QUBITS) {
        d = (x[lane] - y[lane]) * 0.5f;
    }
    float c2 = __cosf(d);          // RRO.SINCOS + MUFU.COS
    c2 *= c2;
    // Warp-wide product reduction (5-level butterfly; inactive lanes hold 1.0).
    #pragma unroll
    for (int off = 16; off > 0; off >>= 1) {
        c2 *= __shfl_xor_sync(0xFFFFFFFFu, c2, off);
    }
    if (lane == 0) {
        out[0] = c2;
    }
}

extern "C" void kernel_launch(void* const* d_in, const int* in_sizes, int n_in,
                              void* d_out, int out_size) {
    (void)in_sizes; (void)n_in; (void)out_size;
    const float* x = (const float*)d_in[0];
    const float* y = (const float*)d_in[1];
    // d_in[2] = params — unused: the shared circuit unitary cancels in the overlap.
    float* out = (float*)d_out;
    KernalAnsatz_65481071409588_kernel<<<1, 32>>>(x, y, out);
}